// round 7
// baseline (speedup 1.0000x reference)
#include <cuda_runtime.h>
#include <cuda_bf16.h>
#include <cstdint>
#include <math.h>

#define Bv 8
#define Cv 128
#define Hv 96
#define Wv 96
#define HWv (Hv * Wv)        // 9216
#define Kv 9
#define KD (Cv * Kv)         // 1152
#define OCOFF 27
#define EPSv 1e-5f

// ---------------- scratch (device globals; no runtime allocation) ----------------
__device__ float  g_xT[(size_t)Bv * HWv * Cv];   // hw-major input (layer 1)
__device__ float  g_o1T[(size_t)Bv * HWv * Cv];  // hw-major layer-1 output
__device__ float  g_wt[Cv * KD];                 // transposed dcn weight, tf32
__device__ float  g_wt2[32 * KD];                // transposed offset weight (27->32 pad), tf32
__device__ int4   g_pidx[Bv * Kv * HWv];
__device__ float4 g_pw[Bv * Kv * HWv];
__device__ float  g_mx[Bv * Cv];
__device__ float  g_av[Bv * Cv];
__device__ float  g_ch[Bv * Cv];

__device__ __forceinline__ float to_tf32(float v) {
    float r;
    asm("cvt.rna.tf32.f32 %0, %1;" : "=f"(r) : "f"(v));
    return r;
}

__device__ __forceinline__ void cpa16(float* sdst, const float* gsrc) {
    unsigned int s = (unsigned int)__cvta_generic_to_shared(sdst);
    asm volatile("cp.async.cg.shared.global [%0], [%1], 16;\n" :: "r"(s), "l"(gsrc));
}

__device__ __forceinline__ void mma_tf32(float* d, const float* a, const float* bfr) {
    asm volatile(
        "mma.sync.aligned.m16n8k8.row.col.f32.tf32.tf32.f32 "
        "{%0,%1,%2,%3}, {%4,%5,%6,%7}, {%8,%9}, {%0,%1,%2,%3};\n"
        : "+f"(d[0]), "+f"(d[1]), "+f"(d[2]), "+f"(d[3])
        : "r"(__float_as_uint(a[0])), "r"(__float_as_uint(a[1])),
          "r"(__float_as_uint(a[2])), "r"(__float_as_uint(a[3])),
          "r"(__float_as_uint(bfr[0])), "r"(__float_as_uint(bfr[1])));
}

#define BAR_SYNC(id)   asm volatile("bar.sync %0, 384;"   :: "r"(id) : "memory")
#define BAR_ARRIVE(id) asm volatile("bar.arrive %0, 384;" :: "r"(id) : "memory")

// ---------------- transpose x: (C, HW) -> (HW, C) per batch ----------------
__global__ void transpose_kernel(const float* __restrict__ src, float* __restrict__ dst) {
    __shared__ float tile[32][33];
    const int b = blockIdx.z;
    const int hw0 = blockIdx.x * 32;
    const int c0  = blockIdx.y * 32;
    const int tx = threadIdx.x, ty = threadIdx.y;   // (32, 8)
    const float* s = src + (size_t)b * Cv * HWv;
    float* d = dst + (size_t)b * HWv * Cv;
#pragma unroll
    for (int i = 0; i < 4; i++)
        tile[ty + i * 8][tx] = s[(size_t)(c0 + ty + i * 8) * HWv + hw0 + tx];
    __syncthreads();
#pragma unroll
    for (int i = 0; i < 4; i++)
        d[(size_t)(hw0 + ty + i * 8) * Cv + c0 + tx] = tile[tx][ty + i * 8];
}

// ---------------- weight transposes (tf32-rounded) ----------------
__global__ void wtrans_kernel(const float* __restrict__ w, float* __restrict__ wt) {
    int t = blockIdx.x * blockDim.x + threadIdx.x;
    if (t >= Cv * KD) return;
    int o = t / KD, r = t % KD, k = r / Cv, i = r % Cv;
    wt[t] = to_tf32(w[((size_t)o * Cv + i) * Kv + k]);
}

__global__ void wtrans_off_kernel(const float* __restrict__ w, float* __restrict__ wt2) {
    int t = blockIdx.x * blockDim.x + threadIdx.x;
    if (t >= 32 * KD) return;
    int o = t / KD, r = t % KD, k = r / Cv, i = r % Cv;
    wt2[t] = (o < OCOFF) ? to_tf32(w[((size_t)o * Cv + i) * Kv + k]) : 0.f;
}

// ================= tile constants =================
#define TBN 128
#define TBK 32
#define NT (KD / TBK)        // 36
#define AS_STRIDE 36
#define BS_STRIDE 36          // n-major B: Bs[n][k]
#define STAGE_A (128 * AS_STRIDE)      // 4608
#define STAGE_BN (128 * BS_STRIDE)     // 4608
#define GEMM_SMEM ((2 * STAGE_A + 2 * STAGE_BN) * 4)   // 73728 B

#define OSTAGE_A (32 * AS_STRIDE)
#define OSTAGE_F (OSTAGE_A + STAGE_BN)
#define OGEMM_SMEM (2 * OSTAGE_F * 4)
#define SOM_STRIDE 132

// ---------------- offset GEMM (tf32, reads xT) + fused prep ----------------
__global__ void __launch_bounds__(256)
off_gemm_prep_kernel(const float* __restrict__ wt2,   // (32, KD) tf32
                     const float* __restrict__ xT,    // (B, HW, C)
                     const float* __restrict__ off_b, // (27)
                     int4* __restrict__ pidx,
                     float4* __restrict__ pw) {
    extern __shared__ float smem[];
    const int b   = blockIdx.y;
    const int n0  = blockIdx.x * TBN;
    const int tid = threadIdx.x;
    const int warp = tid >> 5, lane = tid & 31;
    const int gid = lane >> 2, tig = lane & 3;
    const int q  = lane >> 3, cl = lane & 7;
    const int wm = (warp & 1) * 16;
    const int wn = (warp >> 1) * 32;
    const float* xb = xT + (size_t)b * HWv * Cv;

    float acc[4][4];
#pragma unroll
    for (int j = 0; j < 4; j++)
#pragma unroll
        for (int c = 0; c < 4; c++) acc[j][c] = 0.f;

    auto issueA = [&](int kt) {
        float* As = smem + (kt & 1) * OSTAGE_F;
        const int k0 = kt * TBK;
        int m = tid >> 3, kkv = (tid & 7) << 2;
        cpa16(As + m * AS_STRIDE + kkv, wt2 + (size_t)m * KD + k0 + kkv);
        asm volatile("cp.async.commit_group;\n" ::);
    };

    issueA(0);
    int kt = 0;
    for (int kp = 0; kp < Kv; kp++) {
        const int dyk = kp / 3 - 1, dxk = kp % 3 - 1;

#pragma unroll
        for (int cg = 0; cg < 4; cg++, kt++) {
            if (kt + 1 < NT) {
                issueA(kt + 1);
                asm volatile("cp.async.wait_group 1;\n" ::);
            } else {
                asm volatile("cp.async.wait_group 0;\n" ::);
            }
            float* As = smem + (kt & 1) * OSTAGE_F;
            float* Bs = As + OSTAGE_A;

#pragma unroll
            for (int r = 0; r < 4; r++) {
                int hwl = warp * 16 + r * 4 + q;
                int hw = n0 + hwl;
                int h = hw / Wv, w = hw % Wv;
                bool valid = ((unsigned)(h + dyk) < Hv) && ((unsigned)(w + dxk) < Wv);
                float4 v = make_float4(0.f, 0.f, 0.f, 0.f);
                if (valid) {
                    int idx = hw + dyk * Wv + dxk;
                    v = *(const float4*)(xb + (size_t)idx * Cv + cg * 32 + cl * 4);
                }
                v.x = to_tf32(v.x); v.y = to_tf32(v.y);
                v.z = to_tf32(v.z); v.w = to_tf32(v.w);
                *(float4*)(Bs + hwl * BS_STRIDE + cl * 4) = v;
            }
            __syncthreads();

#pragma unroll
            for (int s = 0; s < 4; s++) {
                const int ks = s * 8;
                float afr[4];
                int m = wm + gid;
                afr[0] = As[m * AS_STRIDE + ks + tig];
                afr[1] = As[(m + 8) * AS_STRIDE + ks + tig];
                afr[2] = As[m * AS_STRIDE + ks + tig + 4];
                afr[3] = As[(m + 8) * AS_STRIDE + ks + tig + 4];
                float bfr[4][2];
#pragma unroll
                for (int nj = 0; nj < 4; nj++) {
                    int n = wn + nj * 8 + gid;
                    bfr[nj][0] = Bs[n * BS_STRIDE + ks + tig];
                    bfr[nj][1] = Bs[n * BS_STRIDE + ks + tig + 4];
                }
#pragma unroll
                for (int nj = 0; nj < 4; nj++)
                    mma_tf32(acc[nj], afr, bfr[nj]);
            }
            __syncthreads();
        }
    }

    // ---- stage om tile (32 x 128) into smem with bias ----
    float* som = smem;
    {
        int o0 = wm + gid, o1r = o0 + 8;
        float bb0 = (o0 < OCOFF) ? off_b[o0] : 0.f;
        float bb1 = (o1r < OCOFF) ? off_b[o1r] : 0.f;
#pragma unroll
        for (int nj = 0; nj < 4; nj++) {
            int ncol = wn + nj * 8 + 2 * tig;
            som[o0 * SOM_STRIDE + ncol]      = acc[nj][0] + bb0;
            som[o0 * SOM_STRIDE + ncol + 1]  = acc[nj][1] + bb0;
            som[o1r * SOM_STRIDE + ncol]     = acc[nj][2] + bb1;
            som[o1r * SOM_STRIDE + ncol + 1] = acc[nj][3] + bb1;
        }
    }
    __syncthreads();

    // ---- prep: pidx / pw for all (k, col) of this tile ----
    for (int t = tid; t < Kv * TBN; t += 256) {
        int k = t / TBN, col = t % TBN;
        int phw = n0 + col;
        int ph = phw / Wv, pwd = phw % Wv;
        float dy = som[(2 * k) * SOM_STRIDE + col];
        float dx = som[(2 * k + 1) * SOM_STRIDE + col];
        float msk = 1.f / (1.f + expf(-som[(18 + k) * SOM_STRIDE + col]));

        float py = (float)ph - 1.f + (float)(k / 3) + dy;
        float px = (float)pwd - 1.f + (float)(k % 3) + dx;
        float y0f = floorf(py), x0f = floorf(px);
        float wy1 = py - y0f, wx1 = px - x0f;
        int y0 = (int)y0f, x0 = (int)x0f;
        int y1 = y0 + 1, x1 = x0 + 1;

        float w00 = (1.f - wy1) * (1.f - wx1) * msk;
        float w01 = (1.f - wy1) * wx1 * msk;
        float w10 = wy1 * (1.f - wx1) * msk;
        float w11 = wy1 * wx1 * msk;

        bool vy0 = (y0 >= 0 && y0 < Hv), vy1 = (y1 >= 0 && y1 < Hv);
        bool vx0 = (x0 >= 0 && x0 < Wv), vx1 = (x1 >= 0 && x1 < Wv);
        if (!(vy0 && vx0)) w00 = 0.f;
        if (!(vy0 && vx1)) w01 = 0.f;
        if (!(vy1 && vx0)) w10 = 0.f;
        if (!(vy1 && vx1)) w11 = 0.f;

        int iy0 = min(max(y0, 0), Hv - 1), iy1 = min(max(y1, 0), Hv - 1);
        int ix0 = min(max(x0, 0), Wv - 1), ix1 = min(max(x1, 0), Wv - 1);

        size_t gi = ((size_t)b * Kv + k) * HWv + phw;
        pidx[gi] = make_int4(iy0 * Wv + ix0, iy0 * Wv + ix1,
                             iy1 * Wv + ix0, iy1 * Wv + ix1);
        pw[gi]   = make_float4(w00, w01, w10, w11);
    }
}

// ---------------- warp-specialized fused gather + tf32 GEMM + bias/BN/ReLU ----------------
// 384 threads: warps 0-7 = consumers (mma), warps 8-11 = producers (gather B tiles).
// B double-buffered; full[s] barrier id = 1+s, empty[s] barrier id = 3+s, count 384.
__global__ void __launch_bounds__(384, 1)
fused_dcn_gemm_kernel(const float* __restrict__ wt,     // (C, KD) tf32
                      const float* __restrict__ xT,     // (B, HW, C)
                      const int4*  __restrict__ pidx,
                      const float4* __restrict__ pw,
                      const float* __restrict__ bias,
                      const float* __restrict__ bn_g,
                      const float* __restrict__ bn_b,
                      const float* __restrict__ bn_m,
                      const float* __restrict__ bn_v,
                      float* __restrict__ out,          // (B,C,HW) or (B,HW,C)
                      int transposed) {
    extern __shared__ float smem[];
    float* Ab = smem;                       // 2 * STAGE_A
    float* Bb = smem + 2 * STAGE_A;         // 2 * STAGE_BN
    const int b   = blockIdx.y;
    const int n0  = blockIdx.x * TBN;
    const int tid = threadIdx.x;
    const int warp = tid >> 5, lane = tid & 31;
    const float* xb = xT + (size_t)b * HWv * Cv;

    if (warp < 8) {
        // ======== CONSUMERS ========
        const int gid = lane >> 2, tig = lane & 3;
        const int wm = (warp & 1) * 64;
        const int wn = (warp >> 1) * 32;

        float acc[4][4][4];
#pragma unroll
        for (int i = 0; i < 4; i++)
#pragma unroll
            for (int j = 0; j < 4; j++)
#pragma unroll
                for (int c = 0; c < 4; c++) acc[i][j][c] = 0.f;

        auto issueA = [&](int kt) {
            float* As = Ab + (kt & 1) * STAGE_A;
            const int k0 = kt * TBK;
#pragma unroll
            for (int r = 0; r < 4; r++) {
                int e = tid + r * 256;
                int m = e >> 3, kkv = (e & 7) << 2;
                cpa16(As + m * AS_STRIDE + kkv, wt + (size_t)m * KD + k0 + kkv);
            }
            asm volatile("cp.async.commit_group;\n" ::);
        };

        issueA(0);
        for (int kt = 0; kt < NT; kt++) {
            asm volatile("cp.async.wait_group 0;\n" ::);
            BAR_SYNC(1 + (kt & 1));            // B(kt) full + A(kt) visible to all consumers
            if (kt + 1 < NT) issueA(kt + 1);   // overlaps mma below

            const float* As = Ab + (kt & 1) * STAGE_A;
            const float* Bs = Bb + (kt & 1) * STAGE_BN;
#pragma unroll
            for (int s = 0; s < 4; s++) {
                const int ks = s * 8;
                float afr[4][4];
#pragma unroll
                for (int mi = 0; mi < 4; mi++) {
                    int m = wm + mi * 16 + gid;
                    afr[mi][0] = As[m * AS_STRIDE + ks + tig];
                    afr[mi][1] = As[(m + 8) * AS_STRIDE + ks + tig];
                    afr[mi][2] = As[m * AS_STRIDE + ks + tig + 4];
                    afr[mi][3] = As[(m + 8) * AS_STRIDE + ks + tig + 4];
                }
                float bfr[4][2];
#pragma unroll
                for (int nj = 0; nj < 4; nj++) {
                    int n = wn + nj * 8 + gid;
                    bfr[nj][0] = Bs[n * BS_STRIDE + ks + tig];
                    bfr[nj][1] = Bs[n * BS_STRIDE + ks + tig + 4];
                }
#pragma unroll
                for (int mi = 0; mi < 4; mi++)
#pragma unroll
                    for (int nj = 0; nj < 4; nj++)
                        mma_tf32(acc[mi][nj], afr[mi], bfr[nj]);
            }
            BAR_ARRIVE(3 + (kt & 1));          // B stage (kt&1) free
        }

        // ---- epilogue: bias + BN + ReLU ----
#pragma unroll
        for (int mi = 0; mi < 4; mi++) {
            int o0 = wm + mi * 16 + gid;
            int o1r = o0 + 8;
            float sc0 = bn_g[o0]  * rsqrtf(bn_v[o0]  + EPSv);
            float sc1 = bn_g[o1r] * rsqrtf(bn_v[o1r] + EPSv);
            float bb0 = bias[o0] - bn_m[o0], bb1 = bias[o1r] - bn_m[o1r];
            float bt0 = bn_b[o0], bt1 = bn_b[o1r];
#pragma unroll
            for (int nj = 0; nj < 4; nj++) {
                int ncol = n0 + wn + nj * 8 + 2 * tig;
                float v00 = fmaxf((acc[mi][nj][0] + bb0) * sc0 + bt0, 0.f);
                float v01 = fmaxf((acc[mi][nj][1] + bb0) * sc0 + bt0, 0.f);
                float v10 = fmaxf((acc[mi][nj][2] + bb1) * sc1 + bt1, 0.f);
                float v11 = fmaxf((acc[mi][nj][3] + bb1) * sc1 + bt1, 0.f);
                if (transposed) {
                    float* ob = out + (size_t)b * HWv * Cv;
                    ob[(size_t)(ncol)     * Cv + o0]  = v00;
                    ob[(size_t)(ncol + 1) * Cv + o0]  = v01;
                    ob[(size_t)(ncol)     * Cv + o1r] = v10;
                    ob[(size_t)(ncol + 1) * Cv + o1r] = v11;
                } else {
                    *(float2*)(out + ((size_t)b * Cv + o0)  * HWv + ncol) = make_float2(v00, v01);
                    *(float2*)(out + ((size_t)b * Cv + o1r) * HWv + ncol) = make_float2(v10, v11);
                }
            }
        }
    } else {
        // ======== PRODUCERS (4 warps, 128 threads; one hw column each) ========
        const int ptid = tid - 256;     // 0..127
        int4   id4 = make_int4(0, 0, 0, 0);
        float4 w4  = make_float4(0.f, 0.f, 0.f, 0.f);

        for (int kt = 0; kt < NT; kt++) {
            const int kp = kt >> 2, cg = kt & 3;
            if (cg == 0) {
                size_t pb = ((size_t)b * Kv + kp) * HWv + n0 + ptid;
                id4 = __ldg(pidx + pb);
                w4  = __ldg(pw + pb);
            }
            if (kt >= 2) BAR_SYNC(3 + (kt & 1));   // wait stage free

            const float* b00 = xb + (size_t)id4.x * Cv + cg * 32;
            const float* b01 = xb + (size_t)id4.y * Cv + cg * 32;
            const float* b10 = xb + (size_t)id4.z * Cv + cg * 32;
            const float* b11 = xb + (size_t)id4.w * Cv + cg * 32;
            float* bd = Bb + (kt & 1) * STAGE_BN + ptid * BS_STRIDE;
#pragma unroll
            for (int j = 0; j < 8; j++) {
                float4 c00 = *(const float4*)(b00 + j * 4);
                float4 c01 = *(const float4*)(b01 + j * 4);
                float4 c10 = *(const float4*)(b10 + j * 4);
                float4 c11 = *(const float4*)(b11 + j * 4);
                float4 v;
                v.x = to_tf32(w4.x * c00.x + w4.y * c01.x + w4.z * c10.x + w4.w * c11.x);
                v.y = to_tf32(w4.x * c00.y + w4.y * c01.y + w4.z * c10.y + w4.w * c11.y);
                v.z = to_tf32(w4.x * c00.z + w4.y * c01.z + w4.z * c10.z + w4.w * c11.z);
                v.w = to_tf32(w4.x * c00.w + w4.y * c01.w + w4.z * c10.w + w4.w * c11.w);
                *(float4*)(bd + j * 4) = v;
            }
            __threadfence_block();
            BAR_ARRIVE(1 + (kt & 1));              // stage full
        }
    }
}

// ---------------- global max/mean pool per (b,c) ----------------
__global__ void pool_kernel(const float* __restrict__ x,
                            float* __restrict__ mx, float* __restrict__ av) {
    int bc = blockIdx.x;
    const float* p = x + (size_t)bc * HWv;
    float vmax = -3.4e38f, vsum = 0.f;
    for (int i = threadIdx.x; i < HWv; i += 256) {
        float t = p[i];
        vmax = fmaxf(vmax, t);
        vsum += t;
    }
    __shared__ float sm[256], ss[256];
    sm[threadIdx.x] = vmax; ss[threadIdx.x] = vsum;
    __syncthreads();
    for (int s = 128; s > 0; s >>= 1) {
        if (threadIdx.x < s) {
            sm[threadIdx.x] = fmaxf(sm[threadIdx.x], sm[threadIdx.x + s]);
            ss[threadIdx.x] += ss[threadIdx.x + s];
        }
        __syncthreads();
    }
    if (threadIdx.x == 0) { mx[bc] = sm[0]; av[bc] = ss[0] * (1.f / HWv); }
}

// ---------------- channel-attention MLP ----------------
__global__ void cam_kernel(const float* __restrict__ mx, const float* __restrict__ av,
                           const float* __restrict__ w1,   // (32,128)
                           const float* __restrict__ w2,   // (128,32)
                           float* __restrict__ ch) {
    int b = blockIdx.x;
    int tid = threadIdx.x;
    __shared__ float smx[128], sav[128], sh[32];
    smx[tid] = mx[b * 128 + tid];
    sav[tid] = av[b * 128 + tid];
    __syncthreads();
    if (tid < 32) {
        float a = 0.f, c = 0.f;
        for (int i = 0; i < 128; i++) {
            float wv = w1[tid * 128 + i];
            a = fmaf(smx[i], wv, a);
            c = fmaf(sav[i], wv, c);
        }
        sh[tid] = fmaxf(a, 0.f) + fmaxf(c, 0.f);
    }
    __syncthreads();
    float o = 0.f;
#pragma unroll
    for (int j = 0; j < 32; j++) o = fmaf(sh[j], w2[tid * 32 + j], o);
    ch[b * 128 + tid] = 1.f / (1.f + expf(-o));
}

// ---------------- in-place channel scale ----------------
__global__ void scale_kernel(float* __restrict__ out, const float* __restrict__ ch) {
    size_t t = (size_t)blockIdx.x * blockDim.x + threadIdx.x;
    if (t >= (size_t)Bv * Cv * HWv) return;
    out[t] *= ch[t / HWv];
}

// ---------------- launch ----------------
extern "C" void kernel_launch(void* const* d_in, const int* in_sizes, int n_in,
                              void* d_out, int out_size) {
    const float* x      = (const float*)d_in[0];
    const float* off_w1 = (const float*)d_in[1];
    const float* off_b1 = (const float*)d_in[2];
    const float* dcn_w1 = (const float*)d_in[3];
    const float* dcn_b1 = (const float*)d_in[4];
    const float* bn_g1  = (const float*)d_in[5];
    const float* bn_b1  = (const float*)d_in[6];
    const float* bn_m1  = (const float*)d_in[7];
    const float* bn_v1  = (const float*)d_in[8];
    const float* off_w2 = (const float*)d_in[9];
    const float* off_b2 = (const float*)d_in[10];
    const float* dcn_w2 = (const float*)d_in[11];
    const float* dcn_b2 = (const float*)d_in[12];
    const float* bn_g2  = (const float*)d_in[13];
    const float* bn_b2  = (const float*)d_in[14];
    const float* bn_m2  = (const float*)d_in[15];
    const float* bn_v2  = (const float*)d_in[16];
    const float* cam_w1 = (const float*)d_in[17];
    const float* cam_w2 = (const float*)d_in[18];
    float* out = (float*)d_out;

    float *xT, *o1T, *wt, *wt2, *mxp, *avp, *chp;
    int4 *pidx; float4 *pw;
    cudaGetSymbolAddress((void**)&xT,   g_xT);
    cudaGetSymbolAddress((void**)&o1T,  g_o1T);
    cudaGetSymbolAddress((void**)&wt,   g_wt);
    cudaGetSymbolAddress((void**)&wt2,  g_wt2);
    cudaGetSymbolAddress((void**)&pidx, g_pidx);
    cudaGetSymbolAddress((void**)&pw,   g_pw);
    cudaGetSymbolAddress((void**)&mxp,  g_mx);
    cudaGetSymbolAddress((void**)&avp,  g_av);
    cudaGetSymbolAddress((void**)&chp,  g_ch);

    cudaFuncSetAttribute(fused_dcn_gemm_kernel,
                         cudaFuncAttributeMaxDynamicSharedMemorySize, GEMM_SMEM);
    cudaFuncSetAttribute(off_gemm_prep_kernel,
                         cudaFuncAttributeMaxDynamicSharedMemorySize, OGEMM_SMEM);

    int  wtGrid  = (Cv * KD + 255) / 256;
    int  wt2Grid = (32 * KD + 255) / 256;
    dim3 trGrid(HWv / 32, Cv / 32, Bv);
    dim3 trBlk(32, 8);
    dim3 gemmGrid(HWv / TBN, Bv);
    int  scaleGrid = (Bv * Cv * HWv + 255) / 256;

    // layer 1 (writes o1T hw-major directly)
    transpose_kernel<<<trGrid, trBlk>>>(x, xT);
    wtrans_off_kernel<<<wt2Grid, 256>>>(off_w1, wt2);
    wtrans_kernel<<<wtGrid, 256>>>(dcn_w1, wt);
    off_gemm_prep_kernel<<<gemmGrid, 256, OGEMM_SMEM>>>(wt2, xT, off_b1, pidx, pw);
    fused_dcn_gemm_kernel<<<gemmGrid, 384, GEMM_SMEM>>>(wt, xT, pidx, pw,
        dcn_b1, bn_g1, bn_b1, bn_m1, bn_v1, o1T, 1);

    // layer 2 (writes channel-major final)
    wtrans_off_kernel<<<wt2Grid, 256>>>(off_w2, wt2);
    wtrans_kernel<<<wtGrid, 256>>>(dcn_w2, wt);
    off_gemm_prep_kernel<<<gemmGrid, 256, OGEMM_SMEM>>>(wt2, o1T, off_b2, pidx, pw);
    fused_dcn_gemm_kernel<<<gemmGrid, 384, GEMM_SMEM>>>(wt, o1T, pidx, pw,
        dcn_b2, bn_g2, bn_b2, bn_m2, bn_v2, out, 0);

    // channel attention
    pool_kernel<<<Bv * Cv, 256>>>(out, mxp, avp);
    cam_kernel<<<Bv, 128>>>(mxp, avp, cam_w1, cam_w2, chp);
    scale_kernel<<<scaleGrid, 256>>>(out, chp);
}

// round 8
// speedup vs baseline: 1.5017x; 1.5017x over previous
#include <cuda_runtime.h>
#include <cuda_bf16.h>
#include <cstdint>
#include <math.h>

#define Bv 8
#define Cv 128
#define Hv 96
#define Wv 96
#define HWv (Hv * Wv)        // 9216
#define Kv 9
#define KD (Cv * Kv)         // 1152
#define OCOFF 27
#define EPSv 1e-5f

// ---------------- scratch (device globals; no runtime allocation) ----------------
__device__ float  g_xT[(size_t)Bv * HWv * Cv];   // hw-major input (layer 1)
__device__ float  g_o1T[(size_t)Bv * HWv * Cv];  // hw-major layer-1 output
__device__ float  g_wt[Cv * KD];                 // transposed dcn weight, tf32, k-permuted
__device__ float  g_wt2[32 * KD];                // transposed offset weight (27->32 pad), tf32, k-permuted
__device__ int4   g_pidx[Bv * Kv * HWv];
__device__ float4 g_pw[Bv * Kv * HWv];
__device__ float  g_mx[Bv * Cv];
__device__ float  g_av[Bv * Cv];
__device__ float  g_ch[Bv * Cv];

__device__ __forceinline__ float to_tf32(float v) {
    float r;
    asm("cvt.rna.tf32.f32 %0, %1;" : "=f"(r) : "f"(v));
    return r;
}

__device__ __forceinline__ void cpa16(float* sdst, const float* gsrc) {
    unsigned int s = (unsigned int)__cvta_generic_to_shared(sdst);
    asm volatile("cp.async.cg.shared.global [%0], [%1], 16;\n" :: "r"(s), "l"(gsrc));
}

__device__ __forceinline__ void mma_tf32(float* d, const float* a, const float* bfr) {
    asm volatile(
        "mma.sync.aligned.m16n8k8.row.col.f32.tf32.tf32.f32 "
        "{%0,%1,%2,%3}, {%4,%5,%6,%7}, {%8,%9}, {%0,%1,%2,%3};\n"
        : "+f"(d[0]), "+f"(d[1]), "+f"(d[2]), "+f"(d[3])
        : "r"(__float_as_uint(a[0])), "r"(__float_as_uint(a[1])),
          "r"(__float_as_uint(a[2])), "r"(__float_as_uint(a[3])),
          "r"(__float_as_uint(bfr[0])), "r"(__float_as_uint(bfr[1])));
}

// ---------------- transpose x: (C, HW) -> (HW, C) per batch ----------------
__global__ void transpose_kernel(const float* __restrict__ src, float* __restrict__ dst) {
    __shared__ float tile[32][33];
    const int b = blockIdx.z;
    const int hw0 = blockIdx.x * 32;
    const int c0  = blockIdx.y * 32;
    const int tx = threadIdx.x, ty = threadIdx.y;   // (32, 8)
    const float* s = src + (size_t)b * Cv * HWv;
    float* d = dst + (size_t)b * HWv * Cv;
#pragma unroll
    for (int i = 0; i < 4; i++)
        tile[ty + i * 8][tx] = s[(size_t)(c0 + ty + i * 8) * HWv + hw0 + tx];
    __syncthreads();
#pragma unroll
    for (int i = 0; i < 4; i++)
        d[(size_t)(hw0 + ty + i * 8) * Cv + c0 + tx] = tile[tx][ty + i * 8];
}

// ---------------- weight transposes (tf32-rounded, k-permuted within 8-groups) ----------------
// smem/gmem position q within an 8-col group holds logical kin = (q%2)*4 + q/2,
// so logical (k, k+4) pairs sit at adjacent positions (2k', 2k'+1) -> LDS.64 fragments.
__global__ void wtrans_kernel(const float* __restrict__ w, float* __restrict__ wt) {
    int t = blockIdx.x * blockDim.x + threadIdx.x;
    if (t >= Cv * KD) return;
    int o = t / KD, col = t % KD;
    int q8 = col & 7;
    int kl = (col & ~7) | (((q8 & 1) << 2) | (q8 >> 1));
    int kp = kl / Cv, i = kl % Cv;
    wt[t] = to_tf32(w[((size_t)o * Cv + i) * Kv + kp]);
}

__global__ void wtrans_off_kernel(const float* __restrict__ w, float* __restrict__ wt2) {
    int t = blockIdx.x * blockDim.x + threadIdx.x;
    if (t >= 32 * KD) return;
    int o = t / KD, col = t % KD;
    int q8 = col & 7;
    int kl = (col & ~7) | (((q8 & 1) << 2) | (q8 >> 1));
    int kp = kl / Cv, i = kl % Cv;
    wt2[t] = (o < OCOFF) ? to_tf32(w[((size_t)o * Cv + i) * Kv + kp]) : 0.f;
}

// ================= tile constants =================
#define TBN 128
#define TBK 32
#define NT (KD / TBK)        // 36
#define AS_STRIDE 36
#define BS_STRIDE 36          // n-major B: Bs[n][k] (logical k)
#define STAGE_A (128 * AS_STRIDE)      // 4608
#define STAGE_B (128 * BS_STRIDE)      // 4608
#define STAGE_F (STAGE_A + STAGE_B)    // 9216
#define GEMM_SMEM (2 * STAGE_F * 4)    // 73728 B

#define OSTAGE_A (32 * AS_STRIDE)          // 1152
#define OSTAGE_F (OSTAGE_A + STAGE_B)      // 5760
#define OGEMM_SMEM (2 * OSTAGE_F * 4)      // 46080 B
#define SOM_STRIDE 132

// A-fragment loader: permuted layout -> two LDS.64 per (mi)
__device__ __forceinline__ void load_afrag(const float* As, int m, int ks, int tig, float* afr) {
    float2 a02 = *(const float2*)(As + m * AS_STRIDE + ks + 2 * tig);
    float2 a13 = *(const float2*)(As + (m + 8) * AS_STRIDE + ks + 2 * tig);
    afr[0] = a02.x; afr[1] = a13.x; afr[2] = a02.y; afr[3] = a13.y;
}

// ---------------- offset GEMM (tf32, reads xT) + fused prep ----------------
__global__ void __launch_bounds__(256)
off_gemm_prep_kernel(const float* __restrict__ wt2,   // (32, KD) tf32 permuted
                     const float* __restrict__ xT,    // (B, HW, C)
                     const float* __restrict__ off_b, // (27)
                     int4* __restrict__ pidx,
                     float4* __restrict__ pw) {
    extern __shared__ float smem[];
    const int b   = blockIdx.y;
    const int n0  = blockIdx.x * TBN;
    const int tid = threadIdx.x;
    const int warp = tid >> 5, lane = tid & 31;
    const int gid = lane >> 2, tig = lane & 3;
    const int q  = lane >> 3, cl = lane & 7;
    const int wm = (warp & 1) * 16;
    const int wn = (warp >> 1) * 32;
    const float* xb = xT + (size_t)b * HWv * Cv;

    float acc[4][4];
#pragma unroll
    for (int j = 0; j < 4; j++)
#pragma unroll
        for (int c = 0; c < 4; c++) acc[j][c] = 0.f;

    auto issueA = [&](int kt) {
        float* As = smem + (kt & 1) * OSTAGE_F;
        const int k0 = kt * TBK;
        int m = tid >> 3, kkv = (tid & 7) << 2;
        cpa16(As + m * AS_STRIDE + kkv, wt2 + (size_t)m * KD + k0 + kkv);
        asm volatile("cp.async.commit_group;\n" ::);
    };

    issueA(0);
    int kt = 0;
    for (int kp = 0; kp < Kv; kp++) {
        const int dyk = kp / 3 - 1, dxk = kp % 3 - 1;

#pragma unroll
        for (int cg = 0; cg < 4; cg++, kt++) {
            if (kt + 1 < NT) {
                issueA(kt + 1);
                asm volatile("cp.async.wait_group 1;\n" ::);
            } else {
                asm volatile("cp.async.wait_group 0;\n" ::);
            }
            float* As = smem + (kt & 1) * OSTAGE_F;
            float* Bs = As + OSTAGE_A;

#pragma unroll
            for (int r = 0; r < 4; r++) {
                int hwl = warp * 16 + r * 4 + q;
                int hw = n0 + hwl;
                int h = hw / Wv, w = hw % Wv;
                bool valid = ((unsigned)(h + dyk) < Hv) && ((unsigned)(w + dxk) < Wv);
                float4 v = make_float4(0.f, 0.f, 0.f, 0.f);
                if (valid) {
                    int idx = hw + dyk * Wv + dxk;
                    v = *(const float4*)(xb + (size_t)idx * Cv + cg * 32 + cl * 4);
                }
                v.x = to_tf32(v.x); v.y = to_tf32(v.y);
                v.z = to_tf32(v.z); v.w = to_tf32(v.w);
                *(float4*)(Bs + hwl * BS_STRIDE + cl * 4) = v;
            }
            __syncthreads();

#pragma unroll
            for (int s = 0; s < 4; s++) {
                const int ks = s * 8;
                float afr[4];
                load_afrag(As, wm + gid, ks, tig, afr);
                float bfr[4][2];
#pragma unroll
                for (int nj = 0; nj < 4; nj++) {
                    int n = wn + nj * 8 + gid;
                    bfr[nj][0] = Bs[n * BS_STRIDE + ks + tig];
                    bfr[nj][1] = Bs[n * BS_STRIDE + ks + tig + 4];
                }
#pragma unroll
                for (int nj = 0; nj < 4; nj++)
                    mma_tf32(acc[nj], afr, bfr[nj]);
            }
            __syncthreads();
        }
    }

    // ---- stage om tile (32 x 128) into smem with bias ----
    float* som = smem;
    {
        int o0 = wm + gid, o1r = o0 + 8;
        float bb0 = (o0 < OCOFF) ? off_b[o0] : 0.f;
        float bb1 = (o1r < OCOFF) ? off_b[o1r] : 0.f;
#pragma unroll
        for (int nj = 0; nj < 4; nj++) {
            int ncol = wn + nj * 8 + 2 * tig;
            som[o0 * SOM_STRIDE + ncol]      = acc[nj][0] + bb0;
            som[o0 * SOM_STRIDE + ncol + 1]  = acc[nj][1] + bb0;
            som[o1r * SOM_STRIDE + ncol]     = acc[nj][2] + bb1;
            som[o1r * SOM_STRIDE + ncol + 1] = acc[nj][3] + bb1;
        }
    }
    __syncthreads();

    // ---- prep: pidx / pw for all (k, col) of this tile ----
    for (int t = tid; t < Kv * TBN; t += 256) {
        int k = t / TBN, col = t % TBN;
        int phw = n0 + col;
        int ph = phw / Wv, pwd = phw % Wv;
        float dy = som[(2 * k) * SOM_STRIDE + col];
        float dx = som[(2 * k + 1) * SOM_STRIDE + col];
        float msk = 1.f / (1.f + expf(-som[(18 + k) * SOM_STRIDE + col]));

        float py = (float)ph - 1.f + (float)(k / 3) + dy;
        float px = (float)pwd - 1.f + (float)(k % 3) + dx;
        float y0f = floorf(py), x0f = floorf(px);
        float wy1 = py - y0f, wx1 = px - x0f;
        int y0 = (int)y0f, x0 = (int)x0f;
        int y1 = y0 + 1, x1 = x0 + 1;

        float w00 = (1.f - wy1) * (1.f - wx1) * msk;
        float w01 = (1.f - wy1) * wx1 * msk;
        float w10 = wy1 * (1.f - wx1) * msk;
        float w11 = wy1 * wx1 * msk;

        bool vy0 = (y0 >= 0 && y0 < Hv), vy1 = (y1 >= 0 && y1 < Hv);
        bool vx0 = (x0 >= 0 && x0 < Wv), vx1 = (x1 >= 0 && x1 < Wv);
        if (!(vy0 && vx0)) w00 = 0.f;
        if (!(vy0 && vx1)) w01 = 0.f;
        if (!(vy1 && vx0)) w10 = 0.f;
        if (!(vy1 && vx1)) w11 = 0.f;

        int iy0 = min(max(y0, 0), Hv - 1), iy1 = min(max(y1, 0), Hv - 1);
        int ix0 = min(max(x0, 0), Wv - 1), ix1 = min(max(x1, 0), Wv - 1);

        size_t gi = ((size_t)b * Kv + k) * HWv + phw;
        pidx[gi] = make_int4(iy0 * Wv + ix0, iy0 * Wv + ix1,
                             iy1 * Wv + ix0, iy1 * Wv + ix1);
        pw[gi]   = make_float4(w00, w01, w10, w11);
    }
}

// ---------------- fused gather(xT) + tf32 GEMM + bias/BN/ReLU ----------------
__global__ void __launch_bounds__(256, 2)
fused_dcn_gemm_kernel(const float* __restrict__ wt,     // (C, KD) tf32 permuted
                      const float* __restrict__ xT,     // (B, HW, C)
                      const int4*  __restrict__ pidx,
                      const float4* __restrict__ pw,
                      const float* __restrict__ bias,
                      const float* __restrict__ bn_g,
                      const float* __restrict__ bn_b,
                      const float* __restrict__ bn_m,
                      const float* __restrict__ bn_v,
                      float* __restrict__ out,          // (B,C,HW) or (B,HW,C)
                      int transposed) {
    extern __shared__ float smem[];
    const int b   = blockIdx.y;
    const int n0  = blockIdx.x * TBN;
    const int tid = threadIdx.x;
    const int warp = tid >> 5, lane = tid & 31;
    const int gid = lane >> 2, tig = lane & 3;
    const int q  = lane >> 3, cl = lane & 7;
    const int wm = (warp & 1) * 64;
    const int wn = (warp >> 1) * 32;
    const float* xb = xT + (size_t)b * HWv * Cv;

    float acc[4][4][4];
#pragma unroll
    for (int i = 0; i < 4; i++)
#pragma unroll
        for (int j = 0; j < 4; j++)
#pragma unroll
            for (int c = 0; c < 4; c++) acc[i][j][c] = 0.f;

    auto issueA = [&](int kt) {
        float* As = smem + (kt & 1) * STAGE_F;
        const int k0 = kt * TBK;
#pragma unroll
        for (int r = 0; r < 4; r++) {
            int e = tid + r * 256;
            int m = e >> 3, kkv = (e & 7) << 2;
            cpa16(As + m * AS_STRIDE + kkv, wt + (size_t)m * KD + k0 + kkv);
        }
        asm volatile("cp.async.commit_group;\n" ::);
    };

    issueA(0);
    for (int kt = 0; kt < NT; kt++) {
        const int kp = kt >> 2, cg = kt & 3;
        if (kt + 1 < NT) {
            issueA(kt + 1);
            asm volatile("cp.async.wait_group 1;\n" ::);
        } else {
            asm volatile("cp.async.wait_group 0;\n" ::);
        }
        float* As = smem + (kt & 1) * STAGE_F;
        float* Bs = As + STAGE_A;

        // ---- B-tile build: 4 rounds, each 4 hw x 32 ch via float4 loads ----
#pragma unroll
        for (int r = 0; r < 4; r++) {
            int hwl = warp * 16 + r * 4 + q;
            size_t pbase = ((size_t)b * Kv + kp) * HWv + n0 + hwl;
            int4   id4 = __ldg(pidx + pbase);
            float4 w4  = __ldg(pw + pbase);
            const float* base = xb + cg * 32 + cl * 4;
            float4 c00 = *(const float4*)(base + (size_t)id4.x * Cv);
            float4 c01 = *(const float4*)(base + (size_t)id4.y * Cv);
            float4 c10 = *(const float4*)(base + (size_t)id4.z * Cv);
            float4 c11 = *(const float4*)(base + (size_t)id4.w * Cv);
            float4 v;
            v.x = to_tf32(w4.x * c00.x + w4.y * c01.x + w4.z * c10.x + w4.w * c11.x);
            v.y = to_tf32(w4.x * c00.y + w4.y * c01.y + w4.z * c10.y + w4.w * c11.y);
            v.z = to_tf32(w4.x * c00.z + w4.y * c01.z + w4.z * c10.z + w4.w * c11.z);
            v.w = to_tf32(w4.x * c00.w + w4.y * c01.w + w4.z * c10.w + w4.w * c11.w);
            *(float4*)(Bs + hwl * BS_STRIDE + cl * 4) = v;
        }
        __syncthreads();

#pragma unroll
        for (int s = 0; s < 4; s++) {
            const int ks = s * 8;
            float afr[4][4];
#pragma unroll
            for (int mi = 0; mi < 4; mi++)
                load_afrag(As, wm + mi * 16 + gid, ks, tig, afr[mi]);
            float bfr[4][2];
#pragma unroll
            for (int nj = 0; nj < 4; nj++) {
                int n = wn + nj * 8 + gid;
                bfr[nj][0] = Bs[n * BS_STRIDE + ks + tig];
                bfr[nj][1] = Bs[n * BS_STRIDE + ks + tig + 4];
            }
#pragma unroll
            for (int mi = 0; mi < 4; mi++)
#pragma unroll
                for (int nj = 0; nj < 4; nj++)
                    mma_tf32(acc[mi][nj], afr[mi], bfr[nj]);
        }
        __syncthreads();
    }

    // ---- epilogue: bias + BN + ReLU ----
#pragma unroll
    for (int mi = 0; mi < 4; mi++) {
        int o0 = wm + mi * 16 + gid;
        int o1r = o0 + 8;
        float sc0 = bn_g[o0]  * rsqrtf(bn_v[o0]  + EPSv);
        float sc1 = bn_g[o1r] * rsqrtf(bn_v[o1r] + EPSv);
        float bb0 = bias[o0] - bn_m[o0], bb1 = bias[o1r] - bn_m[o1r];
        float bt0 = bn_b[o0], bt1 = bn_b[o1r];
#pragma unroll
        for (int nj = 0; nj < 4; nj++) {
            int ncol = n0 + wn + nj * 8 + 2 * tig;
            float v00 = fmaxf((acc[mi][nj][0] + bb0) * sc0 + bt0, 0.f);
            float v01 = fmaxf((acc[mi][nj][1] + bb0) * sc0 + bt0, 0.f);
            float v10 = fmaxf((acc[mi][nj][2] + bb1) * sc1 + bt1, 0.f);
            float v11 = fmaxf((acc[mi][nj][3] + bb1) * sc1 + bt1, 0.f);
            if (transposed) {
                float* ob = out + (size_t)b * HWv * Cv;
                ob[(size_t)(ncol)     * Cv + o0]  = v00;
                ob[(size_t)(ncol + 1) * Cv + o0]  = v01;
                ob[(size_t)(ncol)     * Cv + o1r] = v10;
                ob[(size_t)(ncol + 1) * Cv + o1r] = v11;
            } else {
                *(float2*)(out + ((size_t)b * Cv + o0)  * HWv + ncol) = make_float2(v00, v01);
                *(float2*)(out + ((size_t)b * Cv + o1r) * HWv + ncol) = make_float2(v10, v11);
            }
        }
    }
}

// ---------------- global max/mean pool per (b,c) ----------------
__global__ void pool_kernel(const float* __restrict__ x,
                            float* __restrict__ mx, float* __restrict__ av) {
    int bc = blockIdx.x;
    const float* p = x + (size_t)bc * HWv;
    float vmax = -3.4e38f, vsum = 0.f;
    for (int i = threadIdx.x; i < HWv; i += 256) {
        float t = p[i];
        vmax = fmaxf(vmax, t);
        vsum += t;
    }
    __shared__ float sm[256], ss[256];
    sm[threadIdx.x] = vmax; ss[threadIdx.x] = vsum;
    __syncthreads();
    for (int s = 128; s > 0; s >>= 1) {
        if (threadIdx.x < s) {
            sm[threadIdx.x] = fmaxf(sm[threadIdx.x], sm[threadIdx.x + s]);
            ss[threadIdx.x] += ss[threadIdx.x + s];
        }
        __syncthreads();
    }
    if (threadIdx.x == 0) { mx[bc] = sm[0]; av[bc] = ss[0] * (1.f / HWv); }
}

// ---------------- channel-attention MLP ----------------
__global__ void cam_kernel(const float* __restrict__ mx, const float* __restrict__ av,
                           const float* __restrict__ w1,   // (32,128)
                           const float* __restrict__ w2,   // (128,32)
                           float* __restrict__ ch) {
    int b = blockIdx.x;
    int tid = threadIdx.x;
    __shared__ float smx[128], sav[128], sh[32];
    smx[tid] = mx[b * 128 + tid];
    sav[tid] = av[b * 128 + tid];
    __syncthreads();
    if (tid < 32) {
        float a = 0.f, c = 0.f;
        for (int i = 0; i < 128; i++) {
            float wv = w1[tid * 128 + i];
            a = fmaf(smx[i], wv, a);
            c = fmaf(sav[i], wv, c);
        }
        sh[tid] = fmaxf(a, 0.f) + fmaxf(c, 0.f);
    }
    __syncthreads();
    float o = 0.f;
#pragma unroll
    for (int j = 0; j < 32; j++) o = fmaf(sh[j], w2[tid * 32 + j], o);
    ch[b * 128 + tid] = 1.f / (1.f + expf(-o));
}

// ---------------- in-place channel scale ----------------
__global__ void scale_kernel(float* __restrict__ out, const float* __restrict__ ch) {
    size_t t = (size_t)blockIdx.x * blockDim.x + threadIdx.x;
    if (t >= (size_t)Bv * Cv * HWv) return;
    out[t] *= ch[t / HWv];
}

// ---------------- launch ----------------
extern "C" void kernel_launch(void* const* d_in, const int* in_sizes, int n_in,
                              void* d_out, int out_size) {
    const float* x      = (const float*)d_in[0];
    const float* off_w1 = (const float*)d_in[1];
    const float* off_b1 = (const float*)d_in[2];
    const float* dcn_w1 = (const float*)d_in[3];
    const float* dcn_b1 = (const float*)d_in[4];
    const float* bn_g1  = (const float*)d_in[5];
    const float* bn_b1  = (const float*)d_in[6];
    const float* bn_m1  = (const float*)d_in[7];
    const float* bn_v1  = (const float*)d_in[8];
    const float* off_w2 = (const float*)d_in[9];
    const float* off_b2 = (const float*)d_in[10];
    const float* dcn_w2 = (const float*)d_in[11];
    const float* dcn_b2 = (const float*)d_in[12];
    const float* bn_g2  = (const float*)d_in[13];
    const float* bn_b2  = (const float*)d_in[14];
    const float* bn_m2  = (const float*)d_in[15];
    const float* bn_v2  = (const float*)d_in[16];
    const float* cam_w1 = (const float*)d_in[17];
    const float* cam_w2 = (const float*)d_in[18];
    float* out = (float*)d_out;

    float *xT, *o1T, *wt, *wt2, *mxp, *avp, *chp;
    int4 *pidx; float4 *pw;
    cudaGetSymbolAddress((void**)&xT,   g_xT);
    cudaGetSymbolAddress((void**)&o1T,  g_o1T);
    cudaGetSymbolAddress((void**)&wt,   g_wt);
    cudaGetSymbolAddress((void**)&wt2,  g_wt2);
    cudaGetSymbolAddress((void**)&pidx, g_pidx);
    cudaGetSymbolAddress((void**)&pw,   g_pw);
    cudaGetSymbolAddress((void**)&mxp,  g_mx);
    cudaGetSymbolAddress((void**)&avp,  g_av);
    cudaGetSymbolAddress((void**)&chp,  g_ch);

    cudaFuncSetAttribute(fused_dcn_gemm_kernel,
                         cudaFuncAttributeMaxDynamicSharedMemorySize, GEMM_SMEM);
    cudaFuncSetAttribute(off_gemm_prep_kernel,
                         cudaFuncAttributeMaxDynamicSharedMemorySize, OGEMM_SMEM);

    int  wtGrid  = (Cv * KD + 255) / 256;
    int  wt2Grid = (32 * KD + 255) / 256;
    dim3 trGrid(HWv / 32, Cv / 32, Bv);
    dim3 trBlk(32, 8);
    dim3 gemmGrid(HWv / TBN, Bv);
    int  scaleGrid = (Bv * Cv * HWv + 255) / 256;

    // layer 1 (writes o1T hw-major directly)
    transpose_kernel<<<trGrid, trBlk>>>(x, xT);
    wtrans_off_kernel<<<wt2Grid, 256>>>(off_w1, wt2);
    wtrans_kernel<<<wtGrid, 256>>>(dcn_w1, wt);
    off_gemm_prep_kernel<<<gemmGrid, 256, OGEMM_SMEM>>>(wt2, xT, off_b1, pidx, pw);
    fused_dcn_gemm_kernel<<<gemmGrid, 256, GEMM_SMEM>>>(wt, xT, pidx, pw,
        dcn_b1, bn_g1, bn_b1, bn_m1, bn_v1, o1T, 1);

    // layer 2 (writes channel-major final)
    wtrans_off_kernel<<<wt2Grid, 256>>>(off_w2, wt2);
    wtrans_kernel<<<wtGrid, 256>>>(dcn_w2, wt);
    off_gemm_prep_kernel<<<gemmGrid, 256, OGEMM_SMEM>>>(wt2, o1T, off_b2, pidx, pw);
    fused_dcn_gemm_kernel<<<gemmGrid, 256, GEMM_SMEM>>>(wt, o1T, pidx, pw,
        dcn_b2, bn_g2, bn_b2, bn_m2, bn_v2, out, 0);

    // channel attention
    pool_kernel<<<Bv * Cv, 256>>>(out, mxp, avp);
    cam_kernel<<<Bv, 128>>>(mxp, avp, cam_w1, cam_w2, chp);
    scale_kernel<<<scaleGrid, 256>>>(out, chp);
}

// round 9
// speedup vs baseline: 1.7001x; 1.1321x over previous
#include <cuda_runtime.h>
#include <cuda_bf16.h>
#include <cstdint>
#include <math.h>

#define Bv 8
#define Cv 128
#define Hv 96
#define Wv 96
#define HWv (Hv * Wv)        // 9216
#define Kv 9
#define KD (Cv * Kv)         // 1152
#define OCOFF 27
#define EPSv 1e-5f

// ---------------- scratch (device globals; no runtime allocation) ----------------
__device__ float  g_xT[(size_t)Bv * HWv * Cv];   // hw-major input (layer 1)
__device__ float  g_o1T[(size_t)Bv * HWv * Cv];  // hw-major layer-1 output
__device__ float  g_wt[Cv * KD];                 // transposed dcn weight, tf32
__device__ float  g_wt2[32 * KD];                // transposed offset weight (27->32 pad), tf32
__device__ int4   g_pidx[Bv * Kv * HWv];
__device__ float4 g_pw[Bv * Kv * HWv];
__device__ float  g_mx[Bv * Cv];
__device__ float  g_av[Bv * Cv];
__device__ float  g_ch[Bv * Cv];

__device__ __forceinline__ float to_tf32(float v) {
    float r;
    asm("cvt.rna.tf32.f32 %0, %1;" : "=f"(r) : "f"(v));
    return r;
}

__device__ __forceinline__ void cpa16(float* sdst, const float* gsrc) {
    unsigned int s = (unsigned int)__cvta_generic_to_shared(sdst);
    asm volatile("cp.async.cg.shared.global [%0], [%1], 16;\n" :: "r"(s), "l"(gsrc));
}

__device__ __forceinline__ void mma_tf32(float* d, const float* a, const float* bfr) {
    asm volatile(
        "mma.sync.aligned.m16n8k8.row.col.f32.tf32.tf32.f32 "
        "{%0,%1,%2,%3}, {%4,%5,%6,%7}, {%8,%9}, {%0,%1,%2,%3};\n"
        : "+f"(d[0]), "+f"(d[1]), "+f"(d[2]), "+f"(d[3])
        : "r"(__float_as_uint(a[0])), "r"(__float_as_uint(a[1])),
          "r"(__float_as_uint(a[2])), "r"(__float_as_uint(a[3])),
          "r"(__float_as_uint(bfr[0])), "r"(__float_as_uint(bfr[1])));
}

// ---------------- transpose x: (C, HW) -> (HW, C) per batch ----------------
__global__ void transpose_kernel(const float* __restrict__ src, float* __restrict__ dst) {
    __shared__ float tile[32][33];
    const int b = blockIdx.z;
    const int hw0 = blockIdx.x * 32;
    const int c0  = blockIdx.y * 32;
    const int tx = threadIdx.x, ty = threadIdx.y;   // (32, 8)
    const float* s = src + (size_t)b * Cv * HWv;
    float* d = dst + (size_t)b * HWv * Cv;
#pragma unroll
    for (int i = 0; i < 4; i++)
        tile[ty + i * 8][tx] = s[(size_t)(c0 + ty + i * 8) * HWv + hw0 + tx];
    __syncthreads();
#pragma unroll
    for (int i = 0; i < 4; i++)
        d[(size_t)(hw0 + ty + i * 8) * Cv + c0 + tx] = tile[tx][ty + i * 8];
}

// ---------------- weight transposes (tf32-rounded) ----------------
__global__ void wtrans_kernel(const float* __restrict__ w, float* __restrict__ wt) {
    int t = blockIdx.x * blockDim.x + threadIdx.x;
    if (t >= Cv * KD) return;
    int o = t / KD, r = t % KD, k = r / Cv, i = r % Cv;
    wt[t] = to_tf32(w[((size_t)o * Cv + i) * Kv + k]);
}

__global__ void wtrans_off_kernel(const float* __restrict__ w, float* __restrict__ wt2) {
    int t = blockIdx.x * blockDim.x + threadIdx.x;
    if (t >= 32 * KD) return;
    int o = t / KD, r = t % KD, k = r / Cv, i = r % Cv;
    wt2[t] = (o < OCOFF) ? to_tf32(w[((size_t)o * Cv + i) * Kv + k]) : 0.f;
}

// ================= tile constants =================
#define TBN 128
#define TBK 32
#define NT (KD / TBK)        // 36
#define AS_STRIDE 36
#define BS_STRIDE 36          // n-major B: Bs[n][k]
#define STAGE_A (128 * AS_STRIDE)      // 4608
#define STAGE_B (128 * BS_STRIDE)      // 4608
#define STAGE_F (STAGE_A + STAGE_B)    // 9216
#define GEMM_SMEM (2 * STAGE_F * 4)    // 73728 B

#define OSTAGE_A (32 * AS_STRIDE)          // 1152
#define OSTAGE_F (OSTAGE_A + STAGE_B)      // 5760
#define OGEMM_SMEM (2 * OSTAGE_F * 4)      // 46080 B
#define SOM_STRIDE 132

// ---------------- offset GEMM (tf32, reads xT) + fused prep ----------------
__global__ void __launch_bounds__(256)
off_gemm_prep_kernel(const float* __restrict__ wt2,   // (32, KD) tf32
                     const float* __restrict__ xT,    // (B, HW, C)
                     const float* __restrict__ off_b, // (27)
                     int4* __restrict__ pidx,
                     float4* __restrict__ pw) {
    extern __shared__ float smem[];
    const int b   = blockIdx.y;
    const int n0  = blockIdx.x * TBN;
    const int tid = threadIdx.x;
    const int warp = tid >> 5, lane = tid & 31;
    const int gid = lane >> 2, tig = lane & 3;
    const int q  = lane >> 3, cl = lane & 7;
    const int wm = (warp & 1) * 16;
    const int wn = (warp >> 1) * 32;
    const float* xb = xT + (size_t)b * HWv * Cv;

    float acc[4][4];
#pragma unroll
    for (int j = 0; j < 4; j++)
#pragma unroll
        for (int c = 0; c < 4; c++) acc[j][c] = 0.f;

    auto issueA = [&](int kt) {
        float* As = smem + (kt & 1) * OSTAGE_F;
        const int k0 = kt * TBK;
        int m = tid >> 3, kkv = (tid & 7) << 2;
        cpa16(As + m * AS_STRIDE + kkv, wt2 + (size_t)m * KD + k0 + kkv);
        asm volatile("cp.async.commit_group;\n" ::);
    };

    auto buildB = [&](int kt) {
        const int kp = kt >> 2, cg = kt & 3;
        const int dyk = kp / 3 - 1, dxk = kp % 3 - 1;
        float* Bs = smem + (kt & 1) * OSTAGE_F + OSTAGE_A;
#pragma unroll
        for (int r = 0; r < 4; r++) {
            int hwl = warp * 16 + r * 4 + q;
            int hw = n0 + hwl;
            int h = hw / Wv, w = hw % Wv;
            bool valid = ((unsigned)(h + dyk) < Hv) && ((unsigned)(w + dxk) < Wv);
            float4 v = make_float4(0.f, 0.f, 0.f, 0.f);
            if (valid) {
                int idx = hw + dyk * Wv + dxk;
                v = *(const float4*)(xb + (size_t)idx * Cv + cg * 32 + cl * 4);
            }
            v.x = to_tf32(v.x); v.y = to_tf32(v.y);
            v.z = to_tf32(v.z); v.w = to_tf32(v.w);
            *(float4*)(Bs + hwl * BS_STRIDE + cl * 4) = v;
        }
    };

    issueA(0);
    buildB(0);
    __syncthreads();
    for (int kt = 0; kt < NT; kt++) {
        if (kt + 1 < NT) {
            issueA(kt + 1);
            asm volatile("cp.async.wait_group 1;\n" ::);   // A(kt) landed
            buildB(kt + 1);                                // other buffer; overlaps mma below
        } else {
            asm volatile("cp.async.wait_group 0;\n" ::);
        }
        const float* As = smem + (kt & 1) * OSTAGE_F;
        const float* Bs = As + OSTAGE_A;
#pragma unroll
        for (int s = 0; s < 4; s++) {
            const int ks = s * 8;
            float afr[4];
            int m = wm + gid;
            afr[0] = As[m * AS_STRIDE + ks + tig];
            afr[1] = As[(m + 8) * AS_STRIDE + ks + tig];
            afr[2] = As[m * AS_STRIDE + ks + tig + 4];
            afr[3] = As[(m + 8) * AS_STRIDE + ks + tig + 4];
            float bfr[4][2];
#pragma unroll
            for (int nj = 0; nj < 4; nj++) {
                int n = wn + nj * 8 + gid;
                bfr[nj][0] = Bs[n * BS_STRIDE + ks + tig];
                bfr[nj][1] = Bs[n * BS_STRIDE + ks + tig + 4];
            }
#pragma unroll
            for (int nj = 0; nj < 4; nj++)
                mma_tf32(acc[nj], afr, bfr[nj]);
        }
        __syncthreads();
    }

    // ---- stage om tile (32 x 128) into smem with bias ----
    float* som = smem;
    {
        int o0 = wm + gid, o1r = o0 + 8;
        float bb0 = (o0 < OCOFF) ? off_b[o0] : 0.f;
        float bb1 = (o1r < OCOFF) ? off_b[o1r] : 0.f;
#pragma unroll
        for (int nj = 0; nj < 4; nj++) {
            int ncol = wn + nj * 8 + 2 * tig;
            som[o0 * SOM_STRIDE + ncol]      = acc[nj][0] + bb0;
            som[o0 * SOM_STRIDE + ncol + 1]  = acc[nj][1] + bb0;
            som[o1r * SOM_STRIDE + ncol]     = acc[nj][2] + bb1;
            som[o1r * SOM_STRIDE + ncol + 1] = acc[nj][3] + bb1;
        }
    }
    __syncthreads();

    // ---- prep: pidx / pw for all (k, col) of this tile ----
    for (int t = tid; t < Kv * TBN; t += 256) {
        int k = t / TBN, col = t % TBN;
        int phw = n0 + col;
        int ph = phw / Wv, pwd = phw % Wv;
        float dy = som[(2 * k) * SOM_STRIDE + col];
        float dx = som[(2 * k + 1) * SOM_STRIDE + col];
        float msk = 1.f / (1.f + expf(-som[(18 + k) * SOM_STRIDE + col]));

        float py = (float)ph - 1.f + (float)(k / 3) + dy;
        float px = (float)pwd - 1.f + (float)(k % 3) + dx;
        float y0f = floorf(py), x0f = floorf(px);
        float wy1 = py - y0f, wx1 = px - x0f;
        int y0 = (int)y0f, x0 = (int)x0f;
        int y1 = y0 + 1, x1 = x0 + 1;

        float w00 = (1.f - wy1) * (1.f - wx1) * msk;
        float w01 = (1.f - wy1) * wx1 * msk;
        float w10 = wy1 * (1.f - wx1) * msk;
        float w11 = wy1 * wx1 * msk;

        bool vy0 = (y0 >= 0 && y0 < Hv), vy1 = (y1 >= 0 && y1 < Hv);
        bool vx0 = (x0 >= 0 && x0 < Wv), vx1 = (x1 >= 0 && x1 < Wv);
        if (!(vy0 && vx0)) w00 = 0.f;
        if (!(vy0 && vx1)) w01 = 0.f;
        if (!(vy1 && vx0)) w10 = 0.f;
        if (!(vy1 && vx1)) w11 = 0.f;

        int iy0 = min(max(y0, 0), Hv - 1), iy1 = min(max(y1, 0), Hv - 1);
        int ix0 = min(max(x0, 0), Wv - 1), ix1 = min(max(x1, 0), Wv - 1);

        size_t gi = ((size_t)b * Kv + k) * HWv + phw;
        pidx[gi] = make_int4(iy0 * Wv + ix0, iy0 * Wv + ix1,
                             iy1 * Wv + ix0, iy1 * Wv + ix1);
        pw[gi]   = make_float4(w00, w01, w10, w11);
    }
}

// ---------------- fused gather(xT) + tf32 GEMM + bias/BN/ReLU ----------------
__global__ void __launch_bounds__(256, 2)
fused_dcn_gemm_kernel(const float* __restrict__ wt,     // (C, KD) tf32
                      const float* __restrict__ xT,     // (B, HW, C)
                      const int4*  __restrict__ pidx,
                      const float4* __restrict__ pw,
                      const float* __restrict__ bias,
                      const float* __restrict__ bn_g,
                      const float* __restrict__ bn_b,
                      const float* __restrict__ bn_m,
                      const float* __restrict__ bn_v,
                      float* __restrict__ out,          // (B,C,HW) or (B,HW,C)
                      int transposed) {
    extern __shared__ float smem[];
    const int b   = blockIdx.y;
    const int n0  = blockIdx.x * TBN;
    const int tid = threadIdx.x;
    const int warp = tid >> 5, lane = tid & 31;
    const int gid = lane >> 2, tig = lane & 3;
    const int q  = lane >> 3, cl = lane & 7;
    const int wm = (warp & 1) * 64;
    const int wn = (warp >> 1) * 32;
    const float* xb = xT + (size_t)b * HWv * Cv;

    float acc[4][4][4];
#pragma unroll
    for (int i = 0; i < 4; i++)
#pragma unroll
        for (int j = 0; j < 4; j++)
#pragma unroll
            for (int c = 0; c < 4; c++) acc[i][j][c] = 0.f;

    auto issueA = [&](int kt) {
        float* As = smem + (kt & 1) * STAGE_F;
        const int k0 = kt * TBK;
#pragma unroll
        for (int r = 0; r < 4; r++) {
            int e = tid + r * 256;
            int m = e >> 3, kkv = (e & 7) << 2;
            cpa16(As + m * AS_STRIDE + kkv, wt + (size_t)m * KD + k0 + kkv);
        }
        asm volatile("cp.async.commit_group;\n" ::);
    };

    auto buildB = [&](int kt) {
        const int kp = kt >> 2, cg = kt & 3;
        float* Bs = smem + (kt & 1) * STAGE_F + STAGE_A;
#pragma unroll
        for (int r = 0; r < 4; r++) {
            int hwl = warp * 16 + r * 4 + q;
            size_t pbase = ((size_t)b * Kv + kp) * HWv + n0 + hwl;
            int4   id4 = __ldg(pidx + pbase);
            float4 w4  = __ldg(pw + pbase);
            const float* base = xb + cg * 32 + cl * 4;
            float4 c00 = *(const float4*)(base + (size_t)id4.x * Cv);
            float4 c01 = *(const float4*)(base + (size_t)id4.y * Cv);
            float4 c10 = *(const float4*)(base + (size_t)id4.z * Cv);
            float4 c11 = *(const float4*)(base + (size_t)id4.w * Cv);
            float4 v;
            v.x = to_tf32(w4.x * c00.x + w4.y * c01.x + w4.z * c10.x + w4.w * c11.x);
            v.y = to_tf32(w4.x * c00.y + w4.y * c01.y + w4.z * c10.y + w4.w * c11.y);
            v.z = to_tf32(w4.x * c00.z + w4.y * c01.z + w4.z * c10.z + w4.w * c11.z);
            v.w = to_tf32(w4.x * c00.w + w4.y * c01.w + w4.z * c10.w + w4.w * c11.w);
            *(float4*)(Bs + hwl * BS_STRIDE + cl * 4) = v;
        }
    };

    issueA(0);
    buildB(0);
    __syncthreads();
    for (int kt = 0; kt < NT; kt++) {
        if (kt + 1 < NT) {
            issueA(kt + 1);
            asm volatile("cp.async.wait_group 1;\n" ::);   // A(kt) landed
            buildB(kt + 1);                                // other buffer; overlaps mma across warps
        } else {
            asm volatile("cp.async.wait_group 0;\n" ::);
        }
        const float* As = smem + (kt & 1) * STAGE_F;
        const float* Bs = As + STAGE_A;
#pragma unroll
        for (int s = 0; s < 4; s++) {
            const int ks = s * 8;
            float afr[4][4];
#pragma unroll
            for (int mi = 0; mi < 4; mi++) {
                int m = wm + mi * 16 + gid;
                afr[mi][0] = As[m * AS_STRIDE + ks + tig];
                afr[mi][1] = As[(m + 8) * AS_STRIDE + ks + tig];
                afr[mi][2] = As[m * AS_STRIDE + ks + tig + 4];
                afr[mi][3] = As[(m + 8) * AS_STRIDE + ks + tig + 4];
            }
            float bfr[4][2];
#pragma unroll
            for (int nj = 0; nj < 4; nj++) {
                int n = wn + nj * 8 + gid;
                bfr[nj][0] = Bs[n * BS_STRIDE + ks + tig];
                bfr[nj][1] = Bs[n * BS_STRIDE + ks + tig + 4];
            }
#pragma unroll
            for (int mi = 0; mi < 4; mi++)
#pragma unroll
                for (int nj = 0; nj < 4; nj++)
                    mma_tf32(acc[mi][nj], afr[mi], bfr[nj]);
        }
        __syncthreads();
    }

    // ---- epilogue: bias + BN + ReLU ----
#pragma unroll
    for (int mi = 0; mi < 4; mi++) {
        int o0 = wm + mi * 16 + gid;
        int o1r = o0 + 8;
        float sc0 = bn_g[o0]  * rsqrtf(bn_v[o0]  + EPSv);
        float sc1 = bn_g[o1r] * rsqrtf(bn_v[o1r] + EPSv);
        float bb0 = bias[o0] - bn_m[o0], bb1 = bias[o1r] - bn_m[o1r];
        float bt0 = bn_b[o0], bt1 = bn_b[o1r];
#pragma unroll
        for (int nj = 0; nj < 4; nj++) {
            int ncol = n0 + wn + nj * 8 + 2 * tig;
            float v00 = fmaxf((acc[mi][nj][0] + bb0) * sc0 + bt0, 0.f);
            float v01 = fmaxf((acc[mi][nj][1] + bb0) * sc0 + bt0, 0.f);
            float v10 = fmaxf((acc[mi][nj][2] + bb1) * sc1 + bt1, 0.f);
            float v11 = fmaxf((acc[mi][nj][3] + bb1) * sc1 + bt1, 0.f);
            if (transposed) {
                float* ob = out + (size_t)b * HWv * Cv;
                ob[(size_t)(ncol)     * Cv + o0]  = v00;
                ob[(size_t)(ncol + 1) * Cv + o0]  = v01;
                ob[(size_t)(ncol)     * Cv + o1r] = v10;
                ob[(size_t)(ncol + 1) * Cv + o1r] = v11;
            } else {
                *(float2*)(out + ((size_t)b * Cv + o0)  * HWv + ncol) = make_float2(v00, v01);
                *(float2*)(out + ((size_t)b * Cv + o1r) * HWv + ncol) = make_float2(v10, v11);
            }
        }
    }
}

// ---------------- global max/mean pool per (b,c) ----------------
__global__ void pool_kernel(const float* __restrict__ x,
                            float* __restrict__ mx, float* __restrict__ av) {
    int bc = blockIdx.x;
    const float* p = x + (size_t)bc * HWv;
    float vmax = -3.4e38f, vsum = 0.f;
    for (int i = threadIdx.x; i < HWv; i += 256) {
        float t = p[i];
        vmax = fmaxf(vmax, t);
        vsum += t;
    }
    __shared__ float sm[256], ss[256];
    sm[threadIdx.x] = vmax; ss[threadIdx.x] = vsum;
    __syncthreads();
    for (int s = 128; s > 0; s >>= 1) {
        if (threadIdx.x < s) {
            sm[threadIdx.x] = fmaxf(sm[threadIdx.x], sm[threadIdx.x + s]);
            ss[threadIdx.x] += ss[threadIdx.x + s];
        }
        __syncthreads();
    }
    if (threadIdx.x == 0) { mx[bc] = sm[0]; av[bc] = ss[0] * (1.f / HWv); }
}

// ---------------- channel-attention MLP ----------------
__global__ void cam_kernel(const float* __restrict__ mx, const float* __restrict__ av,
                           const float* __restrict__ w1,   // (32,128)
                           const float* __restrict__ w2,   // (128,32)
                           float* __restrict__ ch) {
    int b = blockIdx.x;
    int tid = threadIdx.x;
    __shared__ float smx[128], sav[128], sh[32];
    smx[tid] = mx[b * 128 + tid];
    sav[tid] = av[b * 128 + tid];
    __syncthreads();
    if (tid < 32) {
        float a = 0.f, c = 0.f;
        for (int i = 0; i < 128; i++) {
            float wv = w1[tid * 128 + i];
            a = fmaf(smx[i], wv, a);
            c = fmaf(sav[i], wv, c);
        }
        sh[tid] = fmaxf(a, 0.f) + fmaxf(c, 0.f);
    }
    __syncthreads();
    float o = 0.f;
#pragma unroll
    for (int j = 0; j < 32; j++) o = fmaf(sh[j], w2[tid * 32 + j], o);
    ch[b * 128 + tid] = 1.f / (1.f + expf(-o));
}

// ---------------- in-place channel scale ----------------
__global__ void scale_kernel(float* __restrict__ out, const float* __restrict__ ch) {
    size_t t = (size_t)blockIdx.x * blockDim.x + threadIdx.x;
    if (t >= (size_t)Bv * Cv * HWv) return;
    out[t] *= ch[t / HWv];
}

// ---------------- launch ----------------
extern "C" void kernel_launch(void* const* d_in, const int* in_sizes, int n_in,
                              void* d_out, int out_size) {
    const float* x      = (const float*)d_in[0];
    const float* off_w1 = (const float*)d_in[1];
    const float* off_b1 = (const float*)d_in[2];
    const float* dcn_w1 = (const float*)d_in[3];
    const float* dcn_b1 = (const float*)d_in[4];
    const float* bn_g1  = (const float*)d_in[5];
    const float* bn_b1  = (const float*)d_in[6];
    const float* bn_m1  = (const float*)d_in[7];
    const float* bn_v1  = (const float*)d_in[8];
    const float* off_w2 = (const float*)d_in[9];
    const float* off_b2 = (const float*)d_in[10];
    const float* dcn_w2 = (const float*)d_in[11];
    const float* dcn_b2 = (const float*)d_in[12];
    const float* bn_g2  = (const float*)d_in[13];
    const float* bn_b2  = (const float*)d_in[14];
    const float* bn_m2  = (const float*)d_in[15];
    const float* bn_v2  = (const float*)d_in[16];
    const float* cam_w1 = (const float*)d_in[17];
    const float* cam_w2 = (const float*)d_in[18];
    float* out = (float*)d_out;

    float *xT, *o1T, *wt, *wt2, *mxp, *avp, *chp;
    int4 *pidx; float4 *pw;
    cudaGetSymbolAddress((void**)&xT,   g_xT);
    cudaGetSymbolAddress((void**)&o1T,  g_o1T);
    cudaGetSymbolAddress((void**)&wt,   g_wt);
    cudaGetSymbolAddress((void**)&wt2,  g_wt2);
    cudaGetSymbolAddress((void**)&pidx, g_pidx);
    cudaGetSymbolAddress((void**)&pw,   g_pw);
    cudaGetSymbolAddress((void**)&mxp,  g_mx);
    cudaGetSymbolAddress((void**)&avp,  g_av);
    cudaGetSymbolAddress((void**)&chp,  g_ch);

    cudaFuncSetAttribute(fused_dcn_gemm_kernel,
                         cudaFuncAttributeMaxDynamicSharedMemorySize, GEMM_SMEM);
    cudaFuncSetAttribute(off_gemm_prep_kernel,
                         cudaFuncAttributeMaxDynamicSharedMemorySize, OGEMM_SMEM);

    int  wtGrid  = (Cv * KD + 255) / 256;
    int  wt2Grid = (32 * KD + 255) / 256;
    dim3 trGrid(HWv / 32, Cv / 32, Bv);
    dim3 trBlk(32, 8);
    dim3 gemmGrid(HWv / TBN, Bv);
    int  scaleGrid = (Bv * Cv * HWv + 255) / 256;

    // layer 1 (writes o1T hw-major directly)
    transpose_kernel<<<trGrid, trBlk>>>(x, xT);
    wtrans_off_kernel<<<wt2Grid, 256>>>(off_w1, wt2);
    wtrans_kernel<<<wtGrid, 256>>>(dcn_w1, wt);
    off_gemm_prep_kernel<<<gemmGrid, 256, OGEMM_SMEM>>>(wt2, xT, off_b1, pidx, pw);
    fused_dcn_gemm_kernel<<<gemmGrid, 256, GEMM_SMEM>>>(wt, xT, pidx, pw,
        dcn_b1, bn_g1, bn_b1, bn_m1, bn_v1, o1T, 1);

    // layer 2 (writes channel-major final)
    wtrans_off_kernel<<<wt2Grid, 256>>>(off_w2, wt2);
    wtrans_kernel<<<wtGrid, 256>>>(dcn_w2, wt);
    off_gemm_prep_kernel<<<gemmGrid, 256, OGEMM_SMEM>>>(wt2, o1T, off_b2, pidx, pw);
    fused_dcn_gemm_kernel<<<gemmGrid, 256, GEMM_SMEM>>>(wt, o1T, pidx, pw,
        dcn_b2, bn_g2, bn_b2, bn_m2, bn_v2, out, 0);

    // channel attention
    pool_kernel<<<Bv * Cv, 256>>>(out, mxp, avp);
    cam_kernel<<<Bv, 128>>>(mxp, avp, cam_w1, cam_w2, chp);
    scale_kernel<<<scaleGrid, 256>>>(out, chp);
}